// round 8
// baseline (speedup 1.0000x reference)
#include <cuda_runtime.h>
#include <stdint.h>

#define BN 64
#define GN 4999
#define PN 50
#define NPOS 5120          // padded positions = 32*160
#define NWRD 160           // mask words per pathway
#define SEGK 160           // positions per lane
#define NBKT 8192
#define NPAD 121           // NPOS - GN

__device__ __align__(16) unsigned d_gbits[2 * GN];        // gene-major pathway bits
__device__ __align__(16) float    d_wt[BN * NPOS];        // sorted |x|^.25, transposed
__device__ __align__(16) unsigned d_masks[BN * PN * NWRD];// position-indexed hit masks

// ---------------------------------------------------------------------------
// K1: gene-major pathway bitmask. Thread per gene, 50 coalesced loads.
// ---------------------------------------------------------------------------
__global__ void pbuild_kernel(const float* __restrict__ pw) {
    const int g = blockIdx.x * blockDim.x + threadIdx.x;
    if (g >= GN) return;
    unsigned w0 = 0, w1 = 0;
    #pragma unroll
    for (int p = 0; p < 32; p++)
        if (pw[(size_t)p * GN + g] > 0.0f) w0 |= 1u << p;
    #pragma unroll
    for (int p = 32; p < PN; p++)
        if (pw[(size_t)p * GN + g] > 0.0f) w1 |= 1u << (p - 32);
    d_gbits[2 * g]     = w0;
    d_gbits[2 * g + 1] = w1;
}

// ---------------------------------------------------------------------------
// K2: per-sample bucket sort + positional mask export. One block per sample.
// Bucket by clamp((4-x)*1024) (monotone with descending x); smem histogram +
// block scan + atomic scatter; insertion sort inside buckets on the full
// unique key (dsc<<13 | idx). Then ballot-transpose gene-major bits into
// position-indexed masks and export w (transposed) + masks to gmem.
// ---------------------------------------------------------------------------
#define ST 1024

// smem layout (bytes), all 16B aligned
#define OFF_KEYS 0                     // u64[5120] = 40960; masks alias after death
#define OFF_HIST 40960                 // u32[8192] = 32768
#define OFF_ORD  73728                 // int[5120] = 20480
#define OFF_GB   94208                 // u32[9998] = 39992 (+8 pad)
#define OFF_WAUX 134208                // u32[32]
#define K2_SMEM  134336

__global__ void __launch_bounds__(ST, 1)
sort_kernel(const float* __restrict__ expr) {
    extern __shared__ char smem[];
    unsigned long long* s_keys = (unsigned long long*)(smem + OFF_KEYS);
    unsigned* s_mask = (unsigned*)(smem + OFF_KEYS);     // alias (after keys die)
    unsigned* s_hist = (unsigned*)(smem + OFF_HIST);
    int*      s_ord  = (int*)(smem + OFF_ORD);
    unsigned* s_gb   = (unsigned*)(smem + OFF_GB);
    unsigned* s_waux = (unsigned*)(smem + OFF_WAUX);

    const int b    = blockIdx.x;
    const int tid  = threadIdx.x;
    const int wid  = tid >> 5;
    const int lane = tid & 31;
    const float* row = expr + (size_t)b * GN;

    // phase 0: gene-major bits -> smem (independent of everything below)
    for (int i = tid; i < 2 * GN; i += ST) s_gb[i] = d_gbits[i];

    // phase 1: zero histogram (8 bins per thread, exclusive ownership)
    ((uint4*)s_hist)[2 * tid]     = make_uint4(0, 0, 0, 0);
    ((uint4*)s_hist)[2 * tid + 1] = make_uint4(0, 0, 0, 0);
    __syncthreads();

    // phase 2: load, keys + buckets, histogram
    unsigned long long key[5];
    int bkt[5];
    #pragma unroll
    for (int j = 0; j < 5; j++) {
        int i = j * ST + tid;
        if (i < GN) {
            float x = row[i];
            unsigned u = __float_as_uint(x);
            u = (u & 0x80000000u) ? ~u : (u | 0x80000000u);   // ascending map
            unsigned dsc = ~u;                                 // descending
            key[j] = ((unsigned long long)dsc << 13) | (unsigned)i;
            int bb = (int)((4.0f - x) * 1024.0f);
            bb = bb < 0 ? 0 : (bb > NBKT - 1 ? NBKT - 1 : bb);
            bkt[j] = bb;
            atomicAdd(&s_hist[bb], 1u);
        } else {
            bkt[j] = -1;
        }
    }
    __syncthreads();

    // phase 3: exclusive scan over 8192 bins (8 per thread, owned bins)
    {
        uint4 h0 = ((uint4*)s_hist)[2 * tid];
        uint4 h1 = ((uint4*)s_hist)[2 * tid + 1];
        unsigned lsum = h0.x + h0.y + h0.z + h0.w + h1.x + h1.y + h1.z + h1.w;
        unsigned v = lsum;
        #pragma unroll
        for (int off = 1; off < 32; off <<= 1) {
            unsigned n = __shfl_up_sync(0xffffffffu, v, off);
            if (lane >= off) v += n;
        }
        if (lane == 31) s_waux[wid] = v;
        __syncthreads();
        if (wid == 0) {
            unsigned wv = s_waux[lane];
            unsigned vv = wv;
            #pragma unroll
            for (int off = 1; off < 32; off <<= 1) {
                unsigned n = __shfl_up_sync(0xffffffffu, vv, off);
                if (lane >= off) vv += n;
            }
            s_waux[lane] = vv - wv;               // exclusive warp bases
        }
        __syncthreads();
        unsigned o = s_waux[wid] + (v - lsum);
        uint4 e0, e1;
        e0.x = o;          e0.y = e0.x + h0.x;  e0.z = e0.y + h0.y;  e0.w = e0.z + h0.z;
        e1.x = e0.w + h0.w; e1.y = e1.x + h1.x; e1.z = e1.y + h1.y;  e1.w = e1.z + h1.z;
        ((uint4*)s_hist)[2 * tid]     = e0;       // own bins only: no hazard
        ((uint4*)s_hist)[2 * tid + 1] = e1;
    }
    __syncthreads();

    // phase 4: scatter
    #pragma unroll
    for (int j = 0; j < 5; j++) {
        if (bkt[j] >= 0) {
            unsigned pos = atomicAdd(&s_hist[bkt[j]], 1u);
            s_keys[pos] = key[j];
        }
    }
    __syncthreads();
    // s_hist[bb] = end offset of bucket bb

    // phase 5: insertion sort within buckets (full unique key), 8 per thread
    #pragma unroll
    for (int q = 0; q < 8; q++) {
        int bb = tid * 8 + q;
        int st = (bb == 0) ? 0 : (int)s_hist[bb - 1];
        int en = (int)s_hist[bb];
        for (int i = st + 1; i < en; i++) {
            unsigned long long k = s_keys[i];
            int j = i - 1;
            while (j >= st && s_keys[j] > k) {
                s_keys[j + 1] = s_keys[j];
                j--;
            }
            s_keys[j + 1] = k;
        }
    }
    __syncthreads();

    // phase 6: materialize order (smem) + w transposed (gmem)
    #pragma unroll
    for (int j = 0; j < 5; j++) {
        int pos = j * ST + tid;
        float wv = 0.0f;
        int idx = 0;
        if (pos < GN) {
            unsigned long long k = s_keys[pos];
            idx = (int)(k & 0x1FFFull);
            unsigned u = ~((unsigned)(k >> 13));
            unsigned absbits = (u & 0x80000000u) ? (u & 0x7FFFFFFFu)
                                                 : ((~u) & 0x7FFFFFFFu);
            wv = sqrtf(sqrtf(__uint_as_float(absbits)));
        }
        s_ord[pos] = idx;                                  // pad -> gene 0 (masked later)
        int tp = (pos % SEGK) * 32 + (pos / SEGK);         // transposed slot
        d_wt[b * NPOS + tp] = wv;                          // pad -> 0
    }
    __syncthreads();                                       // s_keys dead

    // phase 7: ballot-transpose to position-indexed masks (overlay keys)
    #pragma unroll
    for (int t = 0; t < 5; t++) {
        int wi = wid + t * 32;                             // 0..159
        int pos = wi * 32 + lane;
        int g = s_ord[pos];
        unsigned hv0 = s_gb[2 * g];
        unsigned hv1 = s_gb[2 * g + 1];
        unsigned m0 = 0, m1 = 0;
        #pragma unroll
        for (int p = 0; p < 32; p++) {
            unsigned bl = __ballot_sync(0xffffffffu, (hv0 >> p) & 1u);
            if (lane == p) m0 = bl;
        }
        #pragma unroll
        for (int p = 0; p < 18; p++) {
            unsigned bl = __ballot_sync(0xffffffffu, (hv1 >> p) & 1u);
            if (lane == p) m1 = bl;
        }
        // pads: positions >= GN forced hit (w=0): word 156 bits 7+, words 157..159
        unsigned padm = (wi == 156) ? 0xFFFFFF80u : ((wi > 156) ? 0xFFFFFFFFu : 0u);
        s_mask[lane * NWRD + wi] = m0 | padm;
        if (lane < 18) s_mask[(32 + lane) * NWRD + wi] = m1 | padm;
    }
    __syncthreads();

    // phase 8: export masks coalesced
    for (int i = tid; i < PN * NWRD; i += ST)
        d_masks[b * PN * NWRD + i] = s_mask[i];
}

// ---------------------------------------------------------------------------
// K3: enrichment. Grid (BN, 10) x 160 threads; warp w -> pathway part*5 + w.
// Lane owns positions [lane*160, lane*160+160) = mask words [lane*5, lane*5+5),
// kept in registers. w is transposed so lane's k-th element sits at k*32+lane
// (conflict-free LDS). Two lane-local passes + warp scan.
// ---------------------------------------------------------------------------
__global__ void __launch_bounds__(160)
es_kernel(float* __restrict__ out) {
    __shared__ float    s_wt[NPOS];        // 20480 B
    __shared__ unsigned s_m5[5 * NWRD];    //  3200 B

    const int b    = blockIdx.x;
    const int part = blockIdx.y;
    const int tid  = threadIdx.x;
    const int wid  = tid >> 5;
    const int lane = tid & 31;

    for (int i = tid; i < NPOS; i += 160) s_wt[i] = d_wt[b * NPOS + i];
    {
        const unsigned* gm = d_masks + b * PN * NWRD + part * 5 * NWRD;
        for (int i = tid; i < 5 * NWRD; i += 160) s_m5[i] = gm[i];
    }
    __syncthreads();

    // lane's 5 mask words -> registers
    unsigned m[5];
    #pragma unroll
    for (int j = 0; j < 5; j++) m[j] = s_m5[wid * NWRD + lane * 5 + j];

    // ---- pass A: hit count (popc) + hit-weight sum ----
    int c = __popc(m[0]) + __popc(m[1]) + __popc(m[2]) + __popc(m[3]) + __popc(m[4]);
    float hw = 0.0f;
    #pragma unroll
    for (int j = 0; j < 5; j++) {
        unsigned bits = m[j];
        #pragma unroll
        for (int q = 0; q < 32; q++) {
            float wv = s_wt[(j * 32 + q) * 32 + lane];
            if (bits & 1u) hw += wv;
            bits >>= 1;
        }
    }

    // warp totals
    float S = hw;
    int   th = c;
    #pragma unroll
    for (int off = 16; off; off >>= 1) {
        S  += __shfl_xor_sync(0xffffffffu, S, off);
        th += __shfl_xor_sync(0xffffffffu, th, off);
    }
    const int size = th - NPAD;            // pads (all in lane 31) are forced hits

    const float invd = 1.0f / fmaxf((float)(GN - size), 1.0f);
    const float invS = (S > 0.0f) ? (1.0f / S) : 1.0f;

    // exclusive prefix of per-lane net delta -> lane's starting r
    float ld = hw * invS - (float)(SEGK - c) * invd;
    float v = ld;
    #pragma unroll
    for (int off = 1; off < 32; off <<= 1) {
        float n = __shfl_up_sync(0xffffffffu, v, off);
        if (lane >= off) v += n;
    }
    float r = v - ld;                      // exclusive prefix

    // ---- pass B: serial running sum, track first argmax |r| ----
    float best_abs = -1.0f, best_val = 0.0f;
    int   best_idx = 0x7fffffff;
    #pragma unroll
    for (int j = 0; j < 5; j++) {
        unsigned bits = m[j];
        #pragma unroll
        for (int q = 0; q < 32; q++) {
            int k = j * 32 + q;
            float wv = s_wt[k * 32 + lane];
            r = (bits & 1u) ? fmaf(wv, invS, r) : (r - invd);
            bits >>= 1;
            float ar = fabsf(r);
            bool better = ar > best_abs;
            int i = lane * SEGK + k;
            best_abs = better ? ar : best_abs;
            best_val = better ? r  : best_val;
            best_idx = better ? i  : best_idx;
        }
    }

    // cross-lane argmax reduce (tie -> smallest index; pads can never win)
    #pragma unroll
    for (int off = 16; off; off >>= 1) {
        float oa = __shfl_down_sync(0xffffffffu, best_abs, off);
        float ov = __shfl_down_sync(0xffffffffu, best_val, off);
        int   oi = __shfl_down_sync(0xffffffffu, best_idx, off);
        if (oa > best_abs || (oa == best_abs && oi < best_idx)) {
            best_abs = oa; best_val = ov; best_idx = oi;
        }
    }
    if (lane == 0)
        out[b * PN + part * 5 + wid] = (size > 0) ? best_val : 0.0f;
}

// ---------------------------------------------------------------------------
extern "C" void kernel_launch(void* const* d_in, const int* in_sizes, int n_in,
                              void* d_out, int out_size) {
    const float* expr = (const float*)d_in[0];   // [B, G]
    const float* pw   = (const float*)d_in[1];   // [P, G]
    float* out        = (float*)d_out;           // [B, P]

    cudaFuncSetAttribute(sort_kernel,
                         cudaFuncAttributeMaxDynamicSharedMemorySize, K2_SMEM);

    pbuild_kernel<<<(GN + 127) / 128, 128>>>(pw);
    sort_kernel<<<BN, ST, K2_SMEM>>>(expr);
    es_kernel<<<dim3(BN, 10), 160>>>(out);
}

// round 9
// speedup vs baseline: 1.0925x; 1.0925x over previous
#include <cuda_runtime.h>
#include <stdint.h>

#define BN 64
#define GN 4999
#define PN 50
#define NPOS 5120          // padded positions = 32*160
#define NWRD 160           // mask words per pathway
#define SEGK 160           // positions per lane
#define NBKT 8192
#define NPAD 121           // NPOS - GN

__device__ __align__(16) unsigned d_gbits[2 * GN];        // gene-major pathway bits
__device__ __align__(16) float    d_wt[BN * NPOS];        // sorted |x|^.25 (natural order)
__device__ __align__(16) unsigned d_masks[BN * PN * NWRD];// position-indexed hit masks

// ---------------------------------------------------------------------------
// K1: gene-major pathway bitmask. One thread per (gene, word-half): 25 loads.
// ---------------------------------------------------------------------------
__global__ void pbuild_kernel(const float* __restrict__ pw) {
    const int t = blockIdx.x * blockDim.x + threadIdx.x;
    if (t >= 2 * GN) return;
    const int g = t >> 1;
    const int h = t & 1;
    unsigned w = 0;
    const int pbase = h * 32;
    const int pcnt  = h ? (PN - 32) : 32;
    #pragma unroll
    for (int q = 0; q < 32; q++) {
        if (q < pcnt && pw[(size_t)(pbase + q) * GN + g] > 0.0f) w |= 1u << q;
    }
    d_gbits[2 * g + h] = w;
}

// ---------------------------------------------------------------------------
// K2: per-sample bucket sort + positional mask export. One block per sample.
// ---------------------------------------------------------------------------
#define ST 1024

// smem layout (bytes), all 16B aligned
#define OFF_KEYS 0                     // u64[5120] = 40960; masks alias after death
#define OFF_HIST 40960                 // u32[8192] = 32768
#define OFF_ORD  73728                 // int[5120] = 20480
#define OFF_GB   94208                 // u32[9998] = 39992 (+8 pad)
#define OFF_WAUX 134208                // u32[32]
#define K2_SMEM  134336

__global__ void __launch_bounds__(ST, 1)
sort_kernel(const float* __restrict__ expr) {
    extern __shared__ char smem[];
    unsigned long long* s_keys = (unsigned long long*)(smem + OFF_KEYS);
    unsigned* s_mask = (unsigned*)(smem + OFF_KEYS);     // alias (after keys die)
    unsigned* s_hist = (unsigned*)(smem + OFF_HIST);
    int*      s_ord  = (int*)(smem + OFF_ORD);
    unsigned* s_gb   = (unsigned*)(smem + OFF_GB);
    unsigned* s_waux = (unsigned*)(smem + OFF_WAUX);

    const int b    = blockIdx.x;
    const int tid  = threadIdx.x;
    const int wid  = tid >> 5;
    const int lane = tid & 31;
    const float* row = expr + (size_t)b * GN;

    // phase 0: gene-major bits -> smem
    for (int i = tid; i < 2 * GN; i += ST) s_gb[i] = d_gbits[i];

    // phase 1: zero histogram (8 bins per thread, exclusive ownership)
    ((uint4*)s_hist)[2 * tid]     = make_uint4(0, 0, 0, 0);
    ((uint4*)s_hist)[2 * tid + 1] = make_uint4(0, 0, 0, 0);
    __syncthreads();

    // phase 2: load, keys + buckets, histogram
    unsigned long long key[5];
    int bkt[5];
    #pragma unroll
    for (int j = 0; j < 5; j++) {
        int i = j * ST + tid;
        if (i < GN) {
            float x = row[i];
            unsigned u = __float_as_uint(x);
            u = (u & 0x80000000u) ? ~u : (u | 0x80000000u);   // ascending map
            unsigned dsc = ~u;                                 // descending
            key[j] = ((unsigned long long)dsc << 13) | (unsigned)i;
            int bb = (int)((4.0f - x) * 1024.0f);
            bb = bb < 0 ? 0 : (bb > NBKT - 1 ? NBKT - 1 : bb);
            bkt[j] = bb;
            atomicAdd(&s_hist[bb], 1u);
        } else {
            bkt[j] = -1;
        }
    }
    __syncthreads();

    // phase 3: exclusive scan over 8192 bins (8 per thread, owned bins)
    {
        uint4 h0 = ((uint4*)s_hist)[2 * tid];
        uint4 h1 = ((uint4*)s_hist)[2 * tid + 1];
        unsigned lsum = h0.x + h0.y + h0.z + h0.w + h1.x + h1.y + h1.z + h1.w;
        unsigned v = lsum;
        #pragma unroll
        for (int off = 1; off < 32; off <<= 1) {
            unsigned n = __shfl_up_sync(0xffffffffu, v, off);
            if (lane >= off) v += n;
        }
        if (lane == 31) s_waux[wid] = v;
        __syncthreads();
        if (wid == 0) {
            unsigned wv = s_waux[lane];
            unsigned vv = wv;
            #pragma unroll
            for (int off = 1; off < 32; off <<= 1) {
                unsigned n = __shfl_up_sync(0xffffffffu, vv, off);
                if (lane >= off) vv += n;
            }
            s_waux[lane] = vv - wv;               // exclusive warp bases
        }
        __syncthreads();
        unsigned o = s_waux[wid] + (v - lsum);
        uint4 e0, e1;
        e0.x = o;           e0.y = e0.x + h0.x;  e0.z = e0.y + h0.y;  e0.w = e0.z + h0.z;
        e1.x = e0.w + h0.w; e1.y = e1.x + h1.x;  e1.z = e1.y + h1.y;  e1.w = e1.z + h1.z;
        ((uint4*)s_hist)[2 * tid]     = e0;       // own bins only: no hazard
        ((uint4*)s_hist)[2 * tid + 1] = e1;
    }
    __syncthreads();

    // phase 4: scatter
    #pragma unroll
    for (int j = 0; j < 5; j++) {
        if (bkt[j] >= 0) {
            unsigned pos = atomicAdd(&s_hist[bkt[j]], 1u);
            s_keys[pos] = key[j];
        }
    }
    __syncthreads();
    // s_hist[bb] = end offset of bucket bb

    // phase 5: insertion sort within buckets (full unique key), 8 per thread.
    // unroll 1: keep code body small (low-grid I-cache throttle).
    #pragma unroll 1
    for (int q = 0; q < 8; q++) {
        int bb = tid * 8 + q;
        int st = (bb == 0) ? 0 : (int)s_hist[bb - 1];
        int en = (int)s_hist[bb];
        #pragma unroll 1
        for (int i = st + 1; i < en; i++) {
            unsigned long long k = s_keys[i];
            int j = i - 1;
            while (j >= st && s_keys[j] > k) {
                s_keys[j + 1] = s_keys[j];
                j--;
            }
            s_keys[j + 1] = k;
        }
    }
    __syncthreads();

    // phase 6: materialize order (smem) + w in natural order (coalesced gmem)
    #pragma unroll
    for (int j = 0; j < 5; j++) {
        int pos = j * ST + tid;
        float wv = 0.0f;
        int idx = 0;
        if (pos < GN) {
            unsigned long long k = s_keys[pos];
            idx = (int)(k & 0x1FFFull);
            unsigned u = ~((unsigned)(k >> 13));
            unsigned absbits = (u & 0x80000000u) ? (u & 0x7FFFFFFFu)
                                                 : ((~u) & 0x7FFFFFFFu);
            wv = sqrtf(sqrtf(__uint_as_float(absbits)));
        }
        s_ord[pos] = idx;                          // pad -> gene 0 (masked later)
        d_wt[b * NPOS + pos] = wv;                 // coalesced; pad -> 0
    }
    __syncthreads();                               // s_keys dead

    // phase 7: ballot-transpose to position-indexed masks (overlay keys)
    #pragma unroll
    for (int t = 0; t < 5; t++) {
        int wi = wid + t * 32;                     // 0..159
        int pos = wi * 32 + lane;
        int g = s_ord[pos];
        unsigned hv0 = s_gb[2 * g];
        unsigned hv1 = s_gb[2 * g + 1];
        unsigned m0 = 0, m1 = 0;
        #pragma unroll
        for (int p = 0; p < 32; p++) {
            unsigned bl = __ballot_sync(0xffffffffu, (hv0 >> p) & 1u);
            if (lane == p) m0 = bl;
        }
        #pragma unroll
        for (int p = 0; p < 18; p++) {
            unsigned bl = __ballot_sync(0xffffffffu, (hv1 >> p) & 1u);
            if (lane == p) m1 = bl;
        }
        // pads: positions >= GN forced hit (w=0): word 156 bits 7+, words 157..159
        unsigned padm = (wi == 156) ? 0xFFFFFF80u : ((wi > 156) ? 0xFFFFFFFFu : 0u);
        s_mask[lane * NWRD + wi] = m0 | padm;
        if (lane < 18) s_mask[(32 + lane) * NWRD + wi] = m1 | padm;
    }
    __syncthreads();

    // phase 8: export masks coalesced
    for (int i = tid; i < PN * NWRD; i += ST)
        d_masks[b * PN * NWRD + i] = s_mask[i];
}

// ---------------------------------------------------------------------------
// K3: enrichment. Grid (BN, 10) x 160 threads; warp w -> pathway part*5 + w.
// s_wt padded to stride 161 (161 mod 32 == 1): s_wt[lane*161+k] conflict-free.
// Lane's 5 mask words live in registers; 1 LDS per element per pass.
// ---------------------------------------------------------------------------
__global__ void __launch_bounds__(160)
es_kernel(float* __restrict__ out) {
    __shared__ float    s_wt[32 * 161];    // 20608 B, padded stride
    __shared__ unsigned s_m5[5 * NWRD];    //  3200 B

    const int b    = blockIdx.x;
    const int part = blockIdx.y;
    const int tid  = threadIdx.x;
    const int wid  = tid >> 5;
    const int lane = tid & 31;

    // coalesced gmem read, conflict-free smem write (stride-161 rows)
    #pragma unroll
    for (int m = 0; m < 32; m++)
        s_wt[m * 161 + tid] = d_wt[b * NPOS + m * 160 + tid];
    {
        const unsigned* gm = d_masks + b * PN * NWRD + part * 5 * NWRD;
        for (int i = tid; i < 5 * NWRD; i += 160) s_m5[i] = gm[i];
    }
    __syncthreads();

    // lane's 5 mask words -> registers (stride-5: conflict-free)
    unsigned m[5];
    #pragma unroll
    for (int j = 0; j < 5; j++) m[j] = s_m5[wid * NWRD + lane * 5 + j];

    const float* wrow = s_wt + lane * 161;

    // ---- pass A: hit count (popc) + hit-weight sum ----
    int c = __popc(m[0]) + __popc(m[1]) + __popc(m[2]) + __popc(m[3]) + __popc(m[4]);
    float hw = 0.0f;
    #pragma unroll
    for (int j = 0; j < 5; j++) {
        unsigned bits = m[j];
        #pragma unroll
        for (int q = 0; q < 32; q++) {
            float wv = wrow[j * 32 + q];
            if (bits & 1u) hw += wv;
            bits >>= 1;
        }
    }

    // warp totals
    float S = hw;
    int   th = c;
    #pragma unroll
    for (int off = 16; off; off >>= 1) {
        S  += __shfl_xor_sync(0xffffffffu, S, off);
        th += __shfl_xor_sync(0xffffffffu, th, off);
    }
    const int size = th - NPAD;            // pads (all in lane 31) are forced hits

    const float invd = 1.0f / fmaxf((float)(GN - size), 1.0f);
    const float invS = (S > 0.0f) ? (1.0f / S) : 1.0f;

    // exclusive prefix of per-lane net delta -> lane's starting r
    float ld = hw * invS - (float)(SEGK - c) * invd;
    float v = ld;
    #pragma unroll
    for (int off = 1; off < 32; off <<= 1) {
        float n = __shfl_up_sync(0xffffffffu, v, off);
        if (lane >= off) v += n;
    }
    float r = v - ld;                      // exclusive prefix

    // ---- pass B: serial running sum, track first argmax |r| ----
    float best_abs = -1.0f, best_val = 0.0f;
    int   best_idx = 0x7fffffff;
    #pragma unroll
    for (int j = 0; j < 5; j++) {
        unsigned bits = m[j];
        #pragma unroll
        for (int q = 0; q < 32; q++) {
            int k = j * 32 + q;
            float wv = wrow[k];
            r = (bits & 1u) ? fmaf(wv, invS, r) : (r - invd);
            bits >>= 1;
            float ar = fabsf(r);
            bool better = ar > best_abs;
            int i = lane * SEGK + k;
            best_abs = better ? ar : best_abs;
            best_val = better ? r  : best_val;
            best_idx = better ? i  : best_idx;
        }
    }

    // cross-lane argmax reduce (tie -> smallest index; pads can never win)
    #pragma unroll
    for (int off = 16; off; off >>= 1) {
        float oa = __shfl_down_sync(0xffffffffu, best_abs, off);
        float ov = __shfl_down_sync(0xffffffffu, best_val, off);
        int   oi = __shfl_down_sync(0xffffffffu, best_idx, off);
        if (oa > best_abs || (oa == best_abs && oi < best_idx)) {
            best_abs = oa; best_val = ov; best_idx = oi;
        }
    }
    if (lane == 0)
        out[b * PN + part * 5 + wid] = (size > 0) ? best_val : 0.0f;
}

// ---------------------------------------------------------------------------
extern "C" void kernel_launch(void* const* d_in, const int* in_sizes, int n_in,
                              void* d_out, int out_size) {
    const float* expr = (const float*)d_in[0];   // [B, G]
    const float* pw   = (const float*)d_in[1];   // [P, G]
    float* out        = (float*)d_out;           // [B, P]

    cudaFuncSetAttribute(sort_kernel,
                         cudaFuncAttributeMaxDynamicSharedMemorySize, K2_SMEM);

    pbuild_kernel<<<(2 * GN + 255) / 256, 256>>>(pw);
    sort_kernel<<<BN, ST, K2_SMEM>>>(expr);
    es_kernel<<<dim3(BN, 10), 160>>>(out);
}